// round 13
// baseline (speedup 1.0000x reference)
#include <cuda_runtime.h>
#include <math.h>

#define N_ROWS 8192
#define T_COLS 256
#define NBLK2  256           // tail grid: 8 warps x 4 rows x 256 = 8192 rows
#define LOG2E  1.4426950408889634f

// Scratch (allocation-free __device__ globals; zero at load; every execution
// restores invariants => graph-replay safe)
__device__ float g_W[N_ROWS * T_COLS];       // w[row][t] = exp(2*cdf[row][t])
__device__ float g_H[T_COLS * T_COLS];       // H[lab][dur] += ev_i * exp(-2*A_i)
__device__ float g_R[2 * T_COLS * T_COLS];   // R[2d+e][t]: e=0 sum_{d'<d}, e=1 sum_{d'<=d} of H[t][d']
__device__ float g_acc[2];                   // {nll_sum, rank_sum}
__device__ unsigned int g_dcnt;              // MONOTONE tail-entry counter (never reset)
__device__ unsigned int g_bcnt;              // MONOTONE B-completion counter (never reset)
__device__ unsigned int g_tickets;           // tail completion ticket (reset each run)

__device__ __forceinline__ float warp_sum(float v) {
    #pragma unroll
    for (int o = 16; o > 0; o >>= 1) v += __shfl_xor_sync(0xffffffffu, v, o);
    return v;
}

// ---------------------------------------------------------------------------
// Kernel 1: per-row (1 warp/row). Load hazards ONCE, gamma-free exp scan,
// write w = exp(2*cdf) to g_W, scatter H atomic (ev=1), reduce nll.
// ---------------------------------------------------------------------------
__global__ void __launch_bounds__(256) rowscan_kernel(
    const float* __restrict__ hz,
    const int*   __restrict__ dur,
    const int*   __restrict__ ev,
    const int*   __restrict__ lab)
{
    __shared__ float snll[8];
    const int row  = (blockIdx.x * blockDim.x + threadIdx.x) >> 5;
    const int lane = threadIdx.x & 31;
    const int warp = threadIdx.x >> 5;

    const int ev_ = ev[row];
    const int L   = lab[row];
    const int dv  = dur[row];

    const float4* rp = reinterpret_cast<const float4*>(hz + (size_t)row * T_COLS);
    const float4 a = rp[lane * 2];
    const float4 b = rp[lane * 2 + 1];
    float v[8] = {a.x, a.y, a.z, a.w, b.x, b.y, b.z, b.w};

    // gamma-free: N(0,1) data keeps fp32 in range; gamma cancels in the loss
    float e[8], local = 0.0f;
    #pragma unroll
    for (int k = 0; k < 8; k++) { e[k] = __expf(v[k]); local += e[k]; }

    float incl = local;
    #pragma unroll
    for (int o = 1; o < 32; o <<= 1) {
        float u = __shfl_up_sync(0xffffffffu, incl, o);
        if (lane >= o) incl += u;
    }
    const float total = __shfl_sync(0xffffffffu, incl, 31);
    float run = incl - local;

    const float sum_ = total + 1.0f;                       // pad column e^0
    const float s2   = __fdividef(2.0f * LOG2E, sum_);     // exp(2*cdf) = exp2(run*s2)

    const int kk = L & 7;
    float cum_sel = 0.0f, phi_sel = v[0];
    float w[8];
    #pragma unroll
    for (int k = 0; k < 8; k++) {
        run += e[k];
        if (k == kk) { cum_sel = run; phi_sel = v[k]; }
        w[k] = exp2f(run * s2);
    }
    const float cum_at = __shfl_sync(0xffffffffu, cum_sel, L >> 3);
    const float phi_at = __shfl_sync(0xffffffffu, phi_sel, L >> 3);

    // store w row (coalesced float4)
    float4* wp = reinterpret_cast<float4*>(g_W + (size_t)row * T_COLS + lane * 8);
    wp[0] = make_float4(w[0], w[1], w[2], w[3]);
    wp[1] = make_float4(w[4], w[5], w[6], w[7]);

    // nll on every lane (cheap), reduce via lane 0
    const float EPS = 1e-7f;
    const float evf = (ev_ != 0) ? 1.0f : 0.0f;
    const float part1 = phi_at * evf;
    const float part2 = -__logf(sum_ + EPS);
    const float part3 = __logf(fmaxf(sum_ - cum_at, 0.0f) + EPS) * (1.0f - evf);
    const float nll   = -(part1 + part2 + part3);

    if (lane == 0) {
        snll[warp] = nll;
        if (ev_ != 0)
            atomicAdd(&g_H[L * T_COLS + dv], exp2f(-cum_at * s2));   // exp(-2*cdf_at)
    }
    __syncthreads();

    if (threadIdx.x < 8) {
        float p = snll[threadIdx.x];
        #pragma unroll
        for (int o = 4; o > 0; o >>= 1) p += __shfl_xor_sync(0xffu, p, o);
        if (threadIdx.x == 0) atomicAdd(&g_acc[0], p);
    }
}

// ---------------------------------------------------------------------------
// Kernel 2 (tail): blocks 0..31 build R from H (8 columns each) and release
// via monotone g_bcnt; ALL blocks then dot 4 rows/warp against R.
// Run index derived from each block's own monotone entry ticket.
// ---------------------------------------------------------------------------
__global__ void __launch_bounds__(256) tail_kernel(
    const int* __restrict__ dur,
    const int* __restrict__ ev,
    float* __restrict__ out)
{
    __shared__ unsigned int s_run;
    __shared__ float sr[8];
    const int warp = threadIdx.x >> 5;
    const int lane = threadIdx.x & 31;

    if (threadIdx.x == 0) s_run = atomicAdd(&g_dcnt, 1u) / NBLK2;   // this run's index
    __syncthreads();
    const unsigned int run_idx = s_run;

    // ---- B phase: blocks 0..31 build R[2d+e][t] for 8 columns each ----------
    if (blockIdx.x < 32) {
        const int t = blockIdx.x * 8 + warp;
        float4* hp = reinterpret_cast<float4*>(&g_H[t * T_COLS + lane * 8]);
        const float4 h0 = hp[0], h1 = hp[1];
        float h[8] = {h0.x, h0.y, h0.z, h0.w, h1.x, h1.y, h1.z, h1.w};

        float local = 0.0f;
        #pragma unroll
        for (int k = 0; k < 8; k++) local += h[k];

        float incl = local;
        #pragma unroll
        for (int o = 1; o < 32; o <<= 1) {
            float u = __shfl_up_sync(0xffffffffu, incl, o);
            if (lane >= o) incl += u;
        }
        float rn = incl - local;
        #pragma unroll
        for (int k = 0; k < 8; k++) {
            const int d = lane * 8 + k;
            g_R[(2 * d)     * T_COLS + t] = rn;    // sum_{d'<d}
            rn += h[k];
            g_R[(2 * d + 1) * T_COLS + t] = rn;    // sum_{d'<=d}
        }
        hp[0] = make_float4(0.f, 0.f, 0.f, 0.f);   // restore H=0 for next replay
        hp[1] = make_float4(0.f, 0.f, 0.f, 0.f);
        __syncthreads();
        if (threadIdx.x == 0) {
            __threadfence();                        // publish R before release
            atomicAdd(&g_bcnt, 1u);
        }
    }

    // ---- dot phase: 4 rows per warp; issue w + scalar loads BEFORE the wait -
    const int base_row = blockIdx.x * 32 + warp * 4;
    int kjv[4];
    float4 w0[4], w1[4];
    #pragma unroll
    for (int r = 0; r < 4; r++) {
        const int row = base_row + r;
        kjv[r] = 2 * dur[row] + ((ev[row] == 0) ? 1 : 0);
        const float4* wp = reinterpret_cast<const float4*>(g_W + (size_t)row * T_COLS + lane * 8);
        w0[r] = wp[0];
        w1[r] = wp[1];
    }

    // wait for all 32 B-blocks of THIS run (both counters are monotone)
    if (threadIdx.x == 0) {
        const unsigned int target = (run_idx + 1u) * 32u;
        while (atomicAdd(&g_bcnt, 0u) < target) { __nanosleep(32); }
        __threadfence();
    }
    __syncthreads();

    float dot = 0.0f;
    #pragma unroll
    for (int r = 0; r < 4; r++) {
        const float4* Rp = reinterpret_cast<const float4*>(g_R + (size_t)kjv[r] * T_COLS + lane * 8);
        const float4 r0 = Rp[0];
        const float4 r1 = Rp[1];
        dot += w0[r].x * r0.x + w0[r].y * r0.y + w0[r].z * r0.z + w0[r].w * r0.w
             + w1[r].x * r1.x + w1[r].y * r1.y + w1[r].z * r1.z + w1[r].w * r1.w;
    }
    dot = warp_sum(dot);
    if (lane == 0) sr[warp] = dot;
    __syncthreads();

    if (threadIdx.x < 8) {
        float p = sr[threadIdx.x];
        #pragma unroll
        for (int o = 4; o > 0; o >>= 1) p += __shfl_xor_sync(0xffu, p, o);
        if (threadIdx.x == 0) {
            atomicAdd(&g_acc[1], p);
            __threadfence();
            const unsigned int tk = atomicAdd(&g_tickets, 1u);
            if (tk == NBLK2 - 1u) {
                const float nll_sum  = atomicExch(&g_acc[0], 0.0f);
                const float rank_sum = atomicExch(&g_acc[1], 0.0f);
                const float ALPHA = 0.5f;
                out[0] = ALPHA * (nll_sum / (float)N_ROWS)
                       + (1.0f - ALPHA) * (rank_sum / ((float)N_ROWS * (float)N_ROWS));
                atomicExch(&g_tickets, 0u);
            }
        }
    }
}

extern "C" void kernel_launch(void* const* d_in, const int* in_sizes, int n_in,
                              void* d_out, int out_size)
{
    const float* hz  = (const float*)d_in[0];
    const int*   dur = (const int*)  d_in[1];
    const int*   ev  = (const int*)  d_in[2];
    const int*   lab = (const int*)  d_in[3];
    float* out = (float*)d_out;

    rowscan_kernel<<<N_ROWS / 8, 256>>>(hz, dur, ev, lab);
    tail_kernel   <<<NBLK2, 256>>>(dur, ev, out);
}

// round 14
// speedup vs baseline: 1.0152x; 1.0152x over previous
#include <cuda_runtime.h>
#include <math.h>

#define N_ROWS 8192
#define T_COLS 256
#define LOG2E  1.4426950408889634f

// Scratch (allocation-free __device__ globals; zero at load; every execution
// restores invariants => graph-replay safe)
__device__ float g_W[N_ROWS * T_COLS];       // w[row][t] = exp(2*cdf[row][t])
__device__ float g_H[T_COLS * T_COLS];       // H[lab][dur] += ev_i * exp(-2*A_i)
__device__ float g_R[2 * T_COLS * T_COLS];   // R[2d+e][t]: e=0 sum_{d'<d}, e=1 sum_{d'<=d} of H[t][d']
__device__ float g_acc[2];                   // {nll_sum, rank_sum}
__device__ unsigned int g_tickets;           // dot-kernel ticket (reset each run)

__device__ __forceinline__ float warp_sum(float v) {
    #pragma unroll
    for (int o = 16; o > 0; o >>= 1) v += __shfl_xor_sync(0xffffffffu, v, o);
    return v;
}

// ---------------------------------------------------------------------------
// Kernel 1: per-row (1 warp/row). Load hazards ONCE, gamma-free exp scan,
// write w = exp(2*cdf) to g_W, scatter H atomic (ev=1), reduce nll.
// ---------------------------------------------------------------------------
__global__ void __launch_bounds__(256) rowscan_kernel(
    const float* __restrict__ hz,
    const int*   __restrict__ dur,
    const int*   __restrict__ ev,
    const int*   __restrict__ lab)
{
    __shared__ float snll[8];
    const int row  = (blockIdx.x * blockDim.x + threadIdx.x) >> 5;
    const int lane = threadIdx.x & 31;
    const int warp = threadIdx.x >> 5;

    const int ev_ = ev[row];
    const int L   = lab[row];
    const int dv  = dur[row];

    const float4* rp = reinterpret_cast<const float4*>(hz + (size_t)row * T_COLS);
    const float4 a = rp[lane * 2];
    const float4 b = rp[lane * 2 + 1];
    float v[8] = {a.x, a.y, a.z, a.w, b.x, b.y, b.z, b.w};

    // gamma-free: N(0,1) data keeps fp32 in range; gamma cancels in the loss
    float e[8], local = 0.0f;
    #pragma unroll
    for (int k = 0; k < 8; k++) { e[k] = __expf(v[k]); local += e[k]; }

    float incl = local;
    #pragma unroll
    for (int o = 1; o < 32; o <<= 1) {
        float u = __shfl_up_sync(0xffffffffu, incl, o);
        if (lane >= o) incl += u;
    }
    const float total = __shfl_sync(0xffffffffu, incl, 31);
    float run = incl - local;

    const float sum_ = total + 1.0f;                       // pad column e^0
    const float s2   = __fdividef(2.0f * LOG2E, sum_);     // exp(2*cdf) = exp2(run*s2)

    const int kk = L & 7;
    float cum_sel = 0.0f, phi_sel = v[0];
    float w[8];
    #pragma unroll
    for (int k = 0; k < 8; k++) {
        run += e[k];
        if (k == kk) { cum_sel = run; phi_sel = v[k]; }
        w[k] = exp2f(run * s2);
    }
    const float cum_at = __shfl_sync(0xffffffffu, cum_sel, L >> 3);
    const float phi_at = __shfl_sync(0xffffffffu, phi_sel, L >> 3);

    // store w row (coalesced float4)
    float4* wp = reinterpret_cast<float4*>(g_W + (size_t)row * T_COLS + lane * 8);
    wp[0] = make_float4(w[0], w[1], w[2], w[3]);
    wp[1] = make_float4(w[4], w[5], w[6], w[7]);

    // nll on every lane (cheap), reduce via lane 0
    const float EPS = 1e-7f;
    const float evf = (ev_ != 0) ? 1.0f : 0.0f;
    const float part1 = phi_at * evf;
    const float part2 = -__logf(sum_ + EPS);
    const float part3 = __logf(fmaxf(sum_ - cum_at, 0.0f) + EPS) * (1.0f - evf);
    const float nll   = -(part1 + part2 + part3);

    if (lane == 0) {
        snll[warp] = nll;
        if (ev_ != 0)
            atomicAdd(&g_H[L * T_COLS + dv], exp2f(-cum_at * s2));   // exp(-2*cdf_at)
    }
    __syncthreads();

    if (threadIdx.x < 8) {
        float p = snll[threadIdx.x];
        #pragma unroll
        for (int o = 4; o > 0; o >>= 1) p += __shfl_xor_sync(0xffu, p, o);
        if (threadIdx.x == 0) atomicAdd(&g_acc[0], p);
    }
}

// ---------------------------------------------------------------------------
// Kernel 2: one warp per column t (=lab). Contiguous float4 loads over d,
// warp prefix scan, write R[2d+e][t]. Re-zero H. 32 blocks x 256 threads.
// ---------------------------------------------------------------------------
__global__ void __launch_bounds__(256) passB_kernel() {
    const int t    = (blockIdx.x * blockDim.x + threadIdx.x) >> 5;
    const int lane = threadIdx.x & 31;

    float4* hp = reinterpret_cast<float4*>(&g_H[t * T_COLS + lane * 8]);
    const float4 h0 = hp[0], h1 = hp[1];
    float h[8] = {h0.x, h0.y, h0.z, h0.w, h1.x, h1.y, h1.z, h1.w};

    float local = 0.0f;
    #pragma unroll
    for (int k = 0; k < 8; k++) local += h[k];

    float incl = local;
    #pragma unroll
    for (int o = 1; o < 32; o <<= 1) {
        float u = __shfl_up_sync(0xffffffffu, incl, o);
        if (lane >= o) incl += u;
    }
    float run = incl - local;
    #pragma unroll
    for (int k = 0; k < 8; k++) {
        const int d = lane * 8 + k;
        g_R[(2 * d)     * T_COLS + t] = run;   // sum_{d'<d}
        run += h[k];
        g_R[(2 * d + 1) * T_COLS + t] = run;   // sum_{d'<=d}
    }
    hp[0] = make_float4(0.f, 0.f, 0.f, 0.f);   // restore H=0 for next replay
    hp[1] = make_float4(0.f, 0.f, 0.f, 0.f);
}

// ---------------------------------------------------------------------------
// Kernel 3: 4 rows per warp; dot(w_row, R[kj]) -> rank reduce -> ticket out.
// Straight-line: all loads up front (MLP ~12), FMAs, reduce. No waits.
// ---------------------------------------------------------------------------
__global__ void __launch_bounds__(256) dot_kernel(
    const int* __restrict__ dur,
    const int* __restrict__ ev,
    float* __restrict__ out)
{
    __shared__ float sr[8];
    const int warp = threadIdx.x >> 5;
    const int lane = threadIdx.x & 31;
    const int base_row = blockIdx.x * 32 + warp * 4;

    int kjv[4];
    #pragma unroll
    for (int r = 0; r < 4; r++) {
        const int row = base_row + r;
        kjv[r] = 2 * dur[row] + ((ev[row] == 0) ? 1 : 0);
    }

    float4 w0[4], w1[4], r0[4], r1[4];
    #pragma unroll
    for (int r = 0; r < 4; r++) {
        const float4* wp = reinterpret_cast<const float4*>(g_W + (size_t)(base_row + r) * T_COLS + lane * 8);
        w0[r] = wp[0];
        w1[r] = wp[1];
        const float4* Rp = reinterpret_cast<const float4*>(g_R + (size_t)kjv[r] * T_COLS + lane * 8);
        r0[r] = Rp[0];
        r1[r] = Rp[1];
    }

    float dot = 0.0f;
    #pragma unroll
    for (int r = 0; r < 4; r++) {
        dot += w0[r].x * r0[r].x + w0[r].y * r0[r].y + w0[r].z * r0[r].z + w0[r].w * r0[r].w
             + w1[r].x * r1[r].x + w1[r].y * r1[r].y + w1[r].z * r1[r].z + w1[r].w * r1[r].w;
    }
    dot = warp_sum(dot);
    if (lane == 0) sr[warp] = dot;
    __syncthreads();

    if (threadIdx.x < 8) {
        float p = sr[threadIdx.x];
        #pragma unroll
        for (int o = 4; o > 0; o >>= 1) p += __shfl_xor_sync(0xffu, p, o);
        if (threadIdx.x == 0) {
            atomicAdd(&g_acc[1], p);
            __threadfence();
            const unsigned int tk = atomicAdd(&g_tickets, 1u);
            if (tk == (unsigned int)gridDim.x - 1u) {
                const float nll_sum  = atomicExch(&g_acc[0], 0.0f);
                const float rank_sum = atomicExch(&g_acc[1], 0.0f);
                const float ALPHA = 0.5f;
                out[0] = ALPHA * (nll_sum / (float)N_ROWS)
                       + (1.0f - ALPHA) * (rank_sum / ((float)N_ROWS * (float)N_ROWS));
                atomicExch(&g_tickets, 0u);
            }
        }
    }
}

extern "C" void kernel_launch(void* const* d_in, const int* in_sizes, int n_in,
                              void* d_out, int out_size)
{
    const float* hz  = (const float*)d_in[0];
    const int*   dur = (const int*)  d_in[1];
    const int*   ev  = (const int*)  d_in[2];
    const int*   lab = (const int*)  d_in[3];
    float* out = (float*)d_out;

    rowscan_kernel<<<N_ROWS / 8, 256>>>(hz, dur, ev, lab);
    passB_kernel  <<<32, 256>>>();
    dot_kernel    <<<N_ROWS / 32, 256>>>(dur, ev, out);
}